// round 14
// baseline (speedup 1.0000x reference)
#include <cuda_runtime.h>
#include <cuda_bf16.h>
#include <cuda_fp16.h>
#include <math.h>
#include <cstdint>

#define NN 50000
#define NE 400000
#define NEP 450000        // edges + self loops
#define NG 256
#define FMAXC 512
#define BN_EPS 1e-5f
#define NEG 0.2f

// ---------------- scratch (device globals; no allocations) ----------------
__device__ __half g_X16[(size_t)NN * FMAXC];  // projected features (fp16)
__device__ float g_O[(size_t)NN * FMAXC];     // aggregated output (pre-BN)
__device__ __nv_bfloat16 g_Ah[(size_t)NN * FMAXC];
__device__ __nv_bfloat16 g_Al[(size_t)NN * FMAXC];
__device__ __nv_bfloat16 g_Bh[FMAXC * FMAXC];
__device__ __nv_bfloat16 g_Bl[FMAXC * FMAXC];
__device__ float g_T[201 * 512];            // row 200 = dvec (fp32, for logits & dv)
__device__ __half g_T16[201 * 512];         // fp16 copy for gather
__device__ float g_TAs[201 * 4];
__device__ float g_TAd[201 * 4];
__device__ float g_als[NN * 4];
__device__ float g_ald[NN * 4];
__device__ int   g_deg[NN];
__device__ int   g_rowptr[NN + 1];
__device__ int   g_cursor[NN];
__device__ int   g_col[NEP];
__device__ int   g_part[64];
__device__ float g_psums[128 * FMAXC];
__device__ float g_psumsq[128 * FMAXC];
__device__ float g_scale[FMAXC];
__device__ float g_shift[FMAXC];
__device__ int   g_bn_ctr[4];               // zero-initialized; self-resetting
__device__ float g_psum[NG * 128];
__device__ unsigned g_pmax[NG * 128];
__device__ int   g_count[NG];

__device__ __forceinline__ float leaky(float x) { return x >= 0.f ? x : NEG * x; }

__device__ __forceinline__ unsigned enc_f(float f) {
    unsigned u = __float_as_uint(f);
    return (u & 0x80000000u) ? ~u : (u | 0x80000000u);
}
__device__ __forceinline__ float dec_f(unsigned u) {
    return (u & 0x80000000u) ? __uint_as_float(u & 0x7fffffffu) : __uint_as_float(~u);
}

// ---------------- cp.async / mma / ldmatrix helpers (baseline PTX) ----------------
__device__ __forceinline__ uint32_t smem_u32(const void* p) {
    uint32_t a;
    asm("{ .reg .u64 t; cvta.to.shared.u64 t, %1; cvt.u32.u64 %0, t; }" : "=r"(a) : "l"(p));
    return a;
}
__device__ __forceinline__ void cp16(uint32_t dst, const void* src) {
    asm volatile("cp.async.cg.shared.global [%0], [%1], 16;" :: "r"(dst), "l"(src));
}
#define CP_COMMIT() asm volatile("cp.async.commit_group;" ::: "memory")
#define CP_WAIT1()  asm volatile("cp.async.wait_group 1;" ::: "memory")
#define CP_WAIT0()  asm volatile("cp.async.wait_group 0;" ::: "memory")

__device__ __forceinline__ void mma16816(float* c, const uint32_t* a, const uint32_t* b) {
    asm volatile(
        "mma.sync.aligned.m16n8k16.row.col.f32.bf16.bf16.f32 "
        "{%0,%1,%2,%3}, {%4,%5,%6,%7}, {%8,%9}, {%0,%1,%2,%3};"
        : "+f"(c[0]), "+f"(c[1]), "+f"(c[2]), "+f"(c[3])
        : "r"(a[0]), "r"(a[1]), "r"(a[2]), "r"(a[3]), "r"(b[0]), "r"(b[1]));
}
__device__ __forceinline__ void ldsm_x4(uint32_t* r, uint32_t addr) {
    asm volatile("ldmatrix.sync.aligned.m8n8.x4.shared.b16 {%0,%1,%2,%3}, [%4];"
                 : "=r"(r[0]), "=r"(r[1]), "=r"(r[2]), "=r"(r[3]) : "r"(addr));
}
__device__ __forceinline__ void ldsm_x2(uint32_t* r, uint32_t addr) {
    asm volatile("ldmatrix.sync.aligned.m8n8.x2.shared.b16 {%0,%1}, [%2];"
                 : "=r"(r[0]), "=r"(r[1]) : "r"(addr));
}

// ---------------- fp32 -> bf16 hi/lo split conversion (vectorized) ----------------
__global__ void k_cvt_split4(const float4* __restrict__ src, __nv_bfloat162* __restrict__ hi,
                             __nv_bfloat162* __restrict__ lo, int total4) {
    int i = blockIdx.x * blockDim.x + threadIdx.x;
    if (i < total4) {
        float4 v = src[i];
        __nv_bfloat16 hx = __float2bfloat16(v.x), hy = __float2bfloat16(v.y);
        __nv_bfloat16 hz = __float2bfloat16(v.z), hw = __float2bfloat16(v.w);
        hi[2 * i]     = __nv_bfloat162(hx, hy);
        hi[2 * i + 1] = __nv_bfloat162(hz, hw);
        lo[2 * i]     = __nv_bfloat162(__float2bfloat16(v.x - __bfloat162float(hx)),
                                       __float2bfloat16(v.y - __bfloat162float(hy)));
        lo[2 * i + 1] = __nv_bfloat162(__float2bfloat16(v.z - __bfloat162float(hz)),
                                       __float2bfloat16(v.w - __bfloat162float(hw)));
    }
}

// ---------------- layer-0 algebraic tables (T rows 0..199 = types, 200 = dvec) ----
__global__ void __launch_bounds__(512) k_w0_table(const float* __restrict__ emb,
                                                  const float* __restrict__ W0,
                                                  const float* __restrict__ db,
                                                  const float* __restrict__ dw) {
    __shared__ float er[64];
    int r = blockIdx.x, c = threadIdx.x;
    if (c < 64) er[c] = (r < 200) ? (emb[r * 64 + c] + db[c]) : dw[c];
    __syncthreads();
    const float* w = W0 + c * 64;
    float s = 0.f;
#pragma unroll 16
    for (int k = 0; k < 64; ++k) s += er[k] * w[k];
    g_T[r * 512 + c] = s;
    g_T16[r * 512 + c] = __float2half(s);
}
// per-row logits of T (incl. dvec row): outS/outD [201,4]
__global__ void k_alphas(const float* __restrict__ Xp, const float* __restrict__ asrc,
                         const float* __restrict__ adst,
                         float* __restrict__ outS, float* __restrict__ outD) {
    int n = blockIdx.x;
    int w = threadIdx.x >> 5, lane = threadIdx.x & 31;
    const float* xr = Xp + (size_t)n * 512 + w * 128;
    float ss = 0.f, sd = 0.f;
#pragma unroll
    for (int j = 0; j < 4; j++) {
        float v = xr[lane + 32 * j];
        ss += v * asrc[w * 128 + lane + 32 * j];
        sd += v * adst[w * 128 + lane + 32 * j];
    }
#pragma unroll
    for (int off = 16; off; off >>= 1) {
        ss += __shfl_down_sync(0xffffffffu, ss, off);
        sd += __shfl_down_sync(0xffffffffu, sd, off);
    }
    if (lane == 0) { outS[n * 4 + w] = ss; outD[n * 4 + w] = sd; }
}

// ---------- fused gathers: 4 nodes per 512-thread block; warp = (node, head) ------
__global__ void __launch_bounds__(512)
k_gather4(const __half* __restrict__ Xp, const float* __restrict__ bias,
          float* __restrict__ out) {
    int wid = threadIdx.x >> 5, l = threadIdx.x & 31;
    int n = blockIdx.x * 4 + (wid >> 2);
    int h = wid & 3;
    if (n >= NN) return;
    int beg = g_rowptr[n], end = g_rowptr[n + 1];
    float ald_n = g_ald[n * 4 + h];
    int off = h * 128 + l * 4;
    float4 acc = make_float4(0.f, 0.f, 0.f, 0.f);
    float wsum = 0.f;
    for (int base = beg; base < end; base += 32) {
        int cnt = min(32, end - base);
        float w = 0.f; int s = 0;
        if (l < cnt) {
            s = g_col[base + l];
            w = __expf(leaky(g_als[s * 4 + h] + ald_n));
        }
        wsum += w;
        for (int j = 0; j < cnt; ++j) {
            float wj = __shfl_sync(0xffffffffu, w, j);
            int   sj = __shfl_sync(0xffffffffu, s, j);
            uint2 hv = *(const uint2*)(Xp + (size_t)sj * 512 + off);
            float2 f0 = __half22float2(*(__half2*)&hv.x);
            float2 f1 = __half22float2(*(__half2*)&hv.y);
            acc.x += wj * f0.x; acc.y += wj * f0.y;
            acc.z += wj * f1.x; acc.w += wj * f1.y;
        }
    }
#pragma unroll
    for (int o = 16; o; o >>= 1) wsum += __shfl_xor_sync(0xffffffffu, wsum, o);
    float inv = 1.f / wsum;
    float4 bv = *(const float4*)(bias + off);
    *(float4*)(out + (size_t)n * 512 + off) =
        make_float4(acc.x * inv + bv.x, acc.y * inv + bv.y,
                    acc.z * inv + bv.z, acc.w * inv + bv.w);
}

// layer-0: rows AND logits reconstructed from T16/TAs/TAd (all cache-resident)
__global__ void __launch_bounds__(512)
k_gather0(const int* __restrict__ x, const float* __restrict__ depth,
          const float* __restrict__ bias, float* __restrict__ out) {
    int wid = threadIdx.x >> 5, l = threadIdx.x & 31;
    int n = blockIdx.x * 4 + (wid >> 2);
    int h = wid & 3;
    if (n >= NN) return;
    int beg = g_rowptr[n], end = g_rowptr[n + 1];
    int xt_n = __ldg(&x[n]);
    float d_n = __ldg(&depth[n]);
    float ald_n = g_TAd[xt_n * 4 + h] + d_n * g_TAd[200 * 4 + h];
    float tas_dv = g_TAs[200 * 4 + h];
    int off = h * 128 + l * 4;
    float4 dv = *(const float4*)(g_T + 200 * 512 + off);
    float4 acc = make_float4(0.f, 0.f, 0.f, 0.f);
    float wsum = 0.f;
    for (int base = beg; base < end; base += 32) {
        int cnt = min(32, end - base);
        float w = 0.f; int xt = 0; float d = 0.f;
        if (l < cnt) {
            int s = g_col[base + l];
            xt = __ldg(&x[s]);
            d  = __ldg(&depth[s]);
            float als_s = g_TAs[xt * 4 + h] + d * tas_dv;
            w  = __expf(leaky(als_s + ald_n));
        }
        wsum += w;
        for (int j = 0; j < cnt; ++j) {
            float wj = __shfl_sync(0xffffffffu, w, j);
            int   xj = __shfl_sync(0xffffffffu, xt, j);
            float dj = __shfl_sync(0xffffffffu, d, j);
            uint2 hv = *(const uint2*)(g_T16 + xj * 512 + off);
            float2 f0 = __half22float2(*(__half2*)&hv.x);
            float2 f1 = __half22float2(*(__half2*)&hv.y);
            acc.x += wj * (f0.x + dj * dv.x);
            acc.y += wj * (f0.y + dj * dv.y);
            acc.z += wj * (f1.x + dj * dv.z);
            acc.w += wj * (f1.y + dj * dv.w);
        }
    }
#pragma unroll
    for (int o = 16; o; o >>= 1) wsum += __shfl_xor_sync(0xffffffffu, wsum, o);
    float inv = 1.f / wsum;
    float4 bv = *(const float4*)(bias + off);
    *(float4*)(out + (size_t)n * 512 + off) =
        make_float4(acc.x * inv + bv.x, acc.y * inv + bv.y,
                    acc.z * inv + bv.z, acc.w * inv + bv.w);
}

// H=1: 16 nodes/block (512 thr), warp per node; als/ald dense; fp16 X
__global__ void __launch_bounds__(512)
k_gather1(const __half* __restrict__ Xp, const float* __restrict__ bias,
          float* __restrict__ out) {
    int wp = threadIdx.x >> 5, l = threadIdx.x & 31;
    int n = blockIdx.x * 16 + wp;
    if (n >= NN) return;
    int beg = g_rowptr[n], end = g_rowptr[n + 1];
    float ald_n = g_ald[n];
    float4 acc = make_float4(0.f, 0.f, 0.f, 0.f);
    float wsum = 0.f;
    for (int base = beg; base < end; base += 32) {
        int cnt = min(32, end - base);
        float w = 0.f; int s = 0;
        if (l < cnt) {
            s = g_col[base + l];
            w = __expf(leaky(g_als[s] + ald_n));
        }
        wsum += w;
        for (int j = 0; j < cnt; ++j) {
            float wj = __shfl_sync(0xffffffffu, w, j);
            int   sj = __shfl_sync(0xffffffffu, s, j);
            uint2 hv = *(const uint2*)(Xp + (size_t)sj * 128 + l * 4);
            float2 f0 = __half22float2(*(__half2*)&hv.x);
            float2 f1 = __half22float2(*(__half2*)&hv.y);
            acc.x += wj * f0.x; acc.y += wj * f0.y;
            acc.z += wj * f1.x; acc.w += wj * f1.y;
        }
    }
#pragma unroll
    for (int o = 16; o; o >>= 1) wsum += __shfl_xor_sync(0xffffffffu, wsum, o);
    float inv = 1.f / wsum;
    float4 bv = *(const float4*)(bias + l * 4);
    *(float4*)(out + (size_t)n * 128 + l * 4) =
        make_float4(acc.x * inv + bv.x, acc.y * inv + bv.y,
                    acc.z * inv + bv.z, acc.w * inv + bv.w);
}

// ---------------- HMMA GEMM: fp16 C store + fused attention logits ----------------
#define TILE_E 5120          // 128*40 elements per tile
#define STAGE_E (4 * TILE_E) // Ah,Al,Bh,Bl
#define GEMM_SMEM (2 * STAGE_E * 2)
__global__ void __launch_bounds__(256)
k_mma_gemm(const __nv_bfloat16* __restrict__ Ah, const __nv_bfloat16* __restrict__ Al,
           const __nv_bfloat16* __restrict__ Bh, const __nv_bfloat16* __restrict__ Bl,
           __half* __restrict__ C, int M, int N, int K,
           const float* __restrict__ av_s, const float* __restrict__ av_d) {
    extern __shared__ __nv_bfloat16 smem[];
    const int tid = threadIdx.x;
    const int wid = tid >> 5, lane = tid & 31;
    const int gid = lane >> 2, tig = lane & 3;
    const int wr = wid & 3, wc = wid >> 2;
    const int brow = blockIdx.y * 128;
    const int bcol = blockIdx.x * 128;
    const uint32_t sbase = smem_u32(smem);

    const int nc = K >> 5;

    auto load_chunk = [&](int c, int stage) {
        int k0 = c << 5;
        uint32_t sb = sbase + stage * (STAGE_E * 2);
#pragma unroll
        for (int jj = 0; jj < 2; ++jj) {
            int j = tid * 2 + jj;
            int row = j >> 2, kk = j & 3;
            uint32_t doff = (uint32_t)(row * 80 + kk * 16);
            int gm = brow + row; if (gm >= M) gm = M - 1;
            size_t sa = (size_t)gm * K + k0 + kk * 8;
            cp16(sb + doff,              Ah + sa);
            cp16(sb + TILE_E * 2 + doff, Al + sa);
            size_t sbb = (size_t)(bcol + row) * K + k0 + kk * 8;
            cp16(sb + TILE_E * 4 + doff, Bh + sbb);
            cp16(sb + TILE_E * 6 + doff, Bl + sbb);
        }
    };

    float acc[2][8][4];
#pragma unroll
    for (int mt = 0; mt < 2; ++mt)
#pragma unroll
        for (int nt = 0; nt < 8; ++nt)
#pragma unroll
            for (int q = 0; q < 4; ++q) acc[mt][nt][q] = 0.f;

    const uint32_t aoff = (uint32_t)((lane & 15) * 80 + (lane >> 4) * 16);
    const uint32_t boff = (uint32_t)((lane & 7) * 80 + ((lane >> 3) & 1) * 16);

    load_chunk(0, 0); CP_COMMIT();
    load_chunk(1, 1); CP_COMMIT();

    for (int c = 0; c < nc; ++c) {
        if (c < nc - 1) { CP_WAIT1(); } else { CP_WAIT0(); }
        __syncthreads();
        uint32_t stB = sbase + (c & 1) * (STAGE_E * 2);
        uint32_t aA  = stB + (uint32_t)(32 * wr * 80) + aoff;
        uint32_t aAl = aA + TILE_E * 2;
        uint32_t aB  = stB + TILE_E * 4 + (uint32_t)(64 * wc * 80) + boff;
        uint32_t aBl = aB + TILE_E * 2;
#pragma unroll
        for (int ks = 0; ks < 2; ++ks) {
            const uint32_t kb = ks * 32;
            uint32_t ah[2][4], al[2][4];
#pragma unroll
            for (int mt = 0; mt < 2; ++mt) {
                ldsm_x4(ah[mt], aA  + mt * (16 * 80) + kb);
                ldsm_x4(al[mt], aAl + mt * (16 * 80) + kb);
            }
#pragma unroll
            for (int nt = 0; nt < 8; ++nt) {
                uint32_t bh[2], bl[2];
                ldsm_x2(bh, aB  + nt * (8 * 80) + kb);
                ldsm_x2(bl, aBl + nt * (8 * 80) + kb);
#pragma unroll
                for (int mt = 0; mt < 2; ++mt) {
                    mma16816(acc[mt][nt], ah[mt], bh);
                    mma16816(acc[mt][nt], ah[mt], bl);
                    mma16816(acc[mt][nt], al[mt], bh);
                }
            }
        }
        __syncthreads();
        if (c + 2 < nc) { load_chunk(c + 2, c & 1); CP_COMMIT(); }
    }

    // store C (fp16)
#pragma unroll
    for (int mt = 0; mt < 2; ++mt) {
        int r0 = brow + 32 * wr + 16 * mt + gid;
#pragma unroll
        for (int nt = 0; nt < 8; ++nt) {
            int n0 = bcol + 64 * wc + 8 * nt + tig * 2;
            if (r0 < M)
                *(__half2*)(C + (size_t)r0 * N + n0) =
                    __floats2half2_rn(acc[mt][nt][0], acc[mt][nt][1]);
            if (r0 + 8 < M)
                *(__half2*)(C + (size_t)(r0 + 8) * N + n0) =
                    __floats2half2_rn(acc[mt][nt][2], acc[mt][nt][3]);
        }
    }

    // fused attention logits: als[r,h] = sum_col C[r,col]*av_s[col] (head = bcol/128)
    if (av_s) {
        const int HH = N >> 7;
        const int hh = bcol >> 7;
        float pa[2][2] = {{0.f, 0.f}, {0.f, 0.f}};
        float pd[2][2] = {{0.f, 0.f}, {0.f, 0.f}};
#pragma unroll
        for (int nt = 0; nt < 8; ++nt) {
            int lc = bcol + 64 * wc + 8 * nt + tig * 2;
            float as0 = __ldg(&av_s[lc]), as1 = __ldg(&av_s[lc + 1]);
            float ad0 = __ldg(&av_d[lc]), ad1 = __ldg(&av_d[lc + 1]);
#pragma unroll
            for (int mt = 0; mt < 2; ++mt) {
                pa[mt][0] += acc[mt][nt][0] * as0 + acc[mt][nt][1] * as1;
                pa[mt][1] += acc[mt][nt][2] * as0 + acc[mt][nt][3] * as1;
                pd[mt][0] += acc[mt][nt][0] * ad0 + acc[mt][nt][1] * ad1;
                pd[mt][1] += acc[mt][nt][2] * ad0 + acc[mt][nt][3] * ad1;
            }
        }
        float* sa = (float*)smem;        // [2][128]
        float* sd = sa + 256;            // [2][128]
#pragma unroll
        for (int mt = 0; mt < 2; ++mt)
#pragma unroll
            for (int rh = 0; rh < 2; ++rh) {
                float va = pa[mt][rh], vd = pd[mt][rh];
                va += __shfl_xor_sync(0xffffffffu, va, 1);
                va += __shfl_xor_sync(0xffffffffu, va, 2);
                vd += __shfl_xor_sync(0xffffffffu, vd, 1);
                vd += __shfl_xor_sync(0xffffffffu, vd, 2);
                if (tig == 0) {
                    int rl = 32 * wr + 16 * mt + 8 * rh + gid;
                    sa[wc * 128 + rl] = va;
                    sd[wc * 128 + rl] = vd;
                }
            }
        __syncthreads();
        if (tid < 128) {
            int r = brow + tid;
            if (r < M) {
                g_als[r * HH + hh] = sa[tid] + sa[128 + tid];
                g_ald[r * HH + hh] = sd[tid] + sd[128 + tid];
            }
        }
    }
}

// ---------------- graph build (CSR by dst, incl. self loops) ----------------
__global__ void k_init_deg() {
    int i = blockIdx.x * blockDim.x + threadIdx.x;
    if (i < NN) g_deg[i] = 1;
}
__global__ void k_count_deg(const int* __restrict__ ei) {
    int e = blockIdx.x * blockDim.x + threadIdx.x;
    if (e < NE) atomicAdd(&g_deg[ei[NE + e]], 1);
}
__global__ void k_scan_blocks() {
    __shared__ int s[1024];
    int t = threadIdx.x;
    int i = blockIdx.x * 1024 + t;
    int v = (i < NN) ? g_deg[i] : 0;
    s[t] = v;
    __syncthreads();
    for (int off = 1; off < 1024; off <<= 1) {
        int add = (t >= off) ? s[t - off] : 0;
        __syncthreads();
        s[t] += add;
        __syncthreads();
    }
    if (i < NN) g_rowptr[i] = s[t] - v;
    if (t == 1023) g_part[blockIdx.x] = s[t];
}
// add chunk offsets (prefix of g_part computed redundantly per thread — 49 hot values)
__global__ void k_add_off() {
    int i = blockIdx.x * blockDim.x + threadIdx.x;
    if (i < NN) {
        int chunk = i >> 10;
        int off = 0;
        for (int c = 0; c < chunk; ++c) off += g_part[c];
        int r = g_rowptr[i] + off;
        g_rowptr[i] = r;
        g_cursor[i] = r;
    }
    if (i == 0) g_rowptr[NN] = NEP;
}
__global__ void k_fill_col(const int* __restrict__ ei) {
    int e = blockIdx.x * blockDim.x + threadIdx.x;
    if (e < NEP) {
        int s, d;
        if (e < NE) { s = ei[e]; d = ei[NE + e]; }
        else        { s = d = e - NE; }
        int pos = atomicAdd(&g_cursor[d], 1);
        g_col[pos] = s;
    }
}

// -------- batchnorm: partial sums + last-block final reduction (1 launch) --------
// which==2 additionally initializes the pooling arrays (pool_bn runs in a later kernel).
__global__ void k_bn_stats_final(const float* __restrict__ X, int F,
                                 const float* __restrict__ gam,
                                 const float* __restrict__ bet, int which) {
    int t = threadIdx.x, b = blockIdx.x;
    if (which == 2) {
        int gi = b * blockDim.x + t;          // 128*128 = 16384 threads
        g_psum[gi] = 0.f;              g_psum[gi + 16384] = 0.f;
        g_pmax[gi] = 0x00800000u;      g_pmax[gi + 16384] = 0x00800000u;
        if (gi < NG) g_count[gi] = 0;
    }
    const int rpb = (NN + 127) / 128;
    int r0 = b * rpb;
    int r1 = r0 + rpb; if (r1 > NN) r1 = NN;
    float s = 0.f, s2 = 0.f;
    for (int r = r0; r < r1; ++r) {
        float v = X[(size_t)r * F + t];
        s += v; s2 += v * v;
    }
    g_psums[b * F + t] = s;
    g_psumsq[b * F + t] = s2;
    __threadfence();
    __shared__ int lastFlag;
    if (t == 0) lastFlag = (atomicAdd(&g_bn_ctr[which], 1) == 127) ? 1 : 0;
    __syncthreads();
    if (lastFlag) {
        float ss = 0.f, ss2 = 0.f;
        for (int bb = 0; bb < 128; ++bb) {
            ss += g_psums[bb * F + t];
            ss2 += g_psumsq[bb * F + t];
        }
        float m = ss * (1.f / NN);
        float var = ss2 * (1.f / NN) - m * m;
        float sc = gam[t] * rsqrtf(var + BN_EPS);
        g_scale[t] = sc;
        g_shift[t] = bet[t] - m * sc;
        if (t == 0) g_bn_ctr[which] = 0;   // self-reset
    }
}
__global__ void k_bn_elu_split(const float4* __restrict__ X, __nv_bfloat162* __restrict__ hi,
                               __nv_bfloat162* __restrict__ lo, int total4, int fmask4) {
    int i = blockIdx.x * blockDim.x + threadIdx.x;
    if (i < total4) {
        int c4 = (i & fmask4) << 2;
        float4 v = X[i];
        float4 sc = *(const float4*)&g_scale[c4];
        float4 sh = *(const float4*)&g_shift[c4];
        float a = fmaf(v.x, sc.x, sh.x); a = a > 0.f ? a : expm1f(a);
        float b = fmaf(v.y, sc.y, sh.y); b = b > 0.f ? b : expm1f(b);
        float cc = fmaf(v.z, sc.z, sh.z); cc = cc > 0.f ? cc : expm1f(cc);
        float d = fmaf(v.w, sc.w, sh.w); d = d > 0.f ? d : expm1f(d);
        __nv_bfloat16 ha = __float2bfloat16(a), hb = __float2bfloat16(b);
        __nv_bfloat16 hc = __float2bfloat16(cc), hd = __float2bfloat16(d);
        hi[2 * i]     = __nv_bfloat162(ha, hb);
        hi[2 * i + 1] = __nv_bfloat162(hc, hd);
        lo[2 * i]     = __nv_bfloat162(__float2bfloat16(a - __bfloat162float(ha)),
                                       __float2bfloat16(b - __bfloat162float(hb)));
        lo[2 * i + 1] = __nv_bfloat162(__float2bfloat16(cc - __bfloat162float(hc)),
                                       __float2bfloat16(d - __bfloat162float(hd)));
    }
}

// ---------------- pooling (fused final BN+ELU + graph counts) ----------------
__global__ void __launch_bounds__(128)
k_pool_bn(const float* __restrict__ X, const int* __restrict__ batch) {
    int t = threadIdx.x;
    float sc = g_scale[t], sh = g_shift[t];
    int r0 = blockIdx.x * 256;
    int r1 = r0 + 256; if (r1 > NN) r1 = NN;
    if (r0 >= NN) return;
    int cur = batch[r0];
    float s = 0.f, m = -3.4e38f;
    int runlen = 0;
    for (int r = r0; r < r1; ++r) {
        int g = batch[r];
        if (g != cur) {
            atomicAdd(&g_psum[cur * 128 + t], s);
            atomicMax(&g_pmax[cur * 128 + t], enc_f(m));
            if (t == 0) atomicAdd(&g_count[cur], runlen);
            s = 0.f; m = -3.4e38f; cur = g; runlen = 0;
        }
        float v = X[(size_t)r * 128 + t] * sc + sh;
        v = v > 0.f ? v : expm1f(v);
        s += v; m = fmaxf(m, v);
        ++runlen;
    }
    atomicAdd(&g_psum[cur * 128 + t], s);
    atomicMax(&g_pmax[cur * 128 + t], enc_f(m));
    if (t == 0) atomicAdd(&g_count[cur], runlen);
}

// ---------------- classifier ----------------
__global__ void __launch_bounds__(256)
k_classifier(const float* __restrict__ cw1, const float* __restrict__ cb1,
             const float* __restrict__ cw2, const float* __restrict__ cb2,
             float* __restrict__ out) {
    __shared__ float s_emb[256];
    __shared__ float s_hid[256];
    int g = blockIdx.x, t = threadIdx.x;
    if (t < 128) {
        float c = (float)g_count[g];
        c = fmaxf(c, 1.f);
        s_emb[t] = g_psum[g * 128 + t] / c;
        s_emb[128 + t] = dec_f(g_pmax[g * 128 + t]);
    }
    __syncthreads();
    float a = cb1[t];
    const float* wr = cw1 + (size_t)t * 256;
    for (int j = 0; j < 256; j++) a += s_emb[j] * wr[j];
    s_hid[t] = fmaxf(a, 0.f);
    __syncthreads();
    if (t < 20) {
        float o = cb2[t];
        const float* w2 = cw2 + (size_t)t * 256;
        for (int j = 0; j < 256; j++) o += s_hid[j] * w2[j];
        out[g * 20 + t] = o;
    }
}

// ---------------- launch ----------------
extern "C" void kernel_launch(void* const* d_in, const int* in_sizes, int n_in,
                              void* d_out, int out_size) {
    const int*   x     = (const int*)d_in[0];
    const int*   ei    = (const int*)d_in[1];
    const float* depth = (const float*)d_in[2];
    const int*   batch = (const int*)d_in[3];
    const float* embt  = (const float*)d_in[4];
    const float* dw    = (const float*)d_in[5];
    const float* db    = (const float*)d_in[6];
    const float* W0  = (const float*)d_in[7];
    const float* as0 = (const float*)d_in[8];
    const float* ad0 = (const float*)d_in[9];
    const float* b0  = (const float*)d_in[10];
    const float* g0  = (const float*)d_in[11];
    const float* be0 = (const float*)d_in[12];
    const float* W1  = (const float*)d_in[13];
    const float* as1 = (const float*)d_in[14];
    const float* ad1 = (const float*)d_in[15];
    const float* b1  = (const float*)d_in[16];
    const float* g1  = (const float*)d_in[17];
    const float* be1 = (const float*)d_in[18];
    const float* W2  = (const float*)d_in[19];
    const float* as2 = (const float*)d_in[20];
    const float* ad2 = (const float*)d_in[21];
    const float* b2  = (const float*)d_in[22];
    const float* g2  = (const float*)d_in[23];
    const float* be2 = (const float*)d_in[24];
    const float* cw1 = (const float*)d_in[25];
    const float* cb1 = (const float*)d_in[26];
    const float* cw2 = (const float*)d_in[27];
    const float* cb2 = (const float*)d_in[28];
    float* out = (float*)d_out;

    float *pO = nullptr, *pT = nullptr;
    float *pTAs = nullptr, *pTAd = nullptr;
    __half *pX16 = nullptr;
    __nv_bfloat16 *pAh = nullptr, *pAl = nullptr, *pBh = nullptr, *pBl = nullptr;
    cudaGetSymbolAddress((void**)&pX16, g_X16);
    cudaGetSymbolAddress((void**)&pO, g_O);
    cudaGetSymbolAddress((void**)&pT, g_T);
    cudaGetSymbolAddress((void**)&pTAs, g_TAs);
    cudaGetSymbolAddress((void**)&pTAd, g_TAd);
    cudaGetSymbolAddress((void**)&pAh, g_Ah);
    cudaGetSymbolAddress((void**)&pAl, g_Al);
    cudaGetSymbolAddress((void**)&pBh, g_Bh);
    cudaGetSymbolAddress((void**)&pBl, g_Bl);

    cudaFuncSetAttribute(k_mma_gemm, cudaFuncAttributeMaxDynamicSharedMemorySize, GEMM_SMEM);

    const int MB = (NN + 127) / 128;

    // CSR build (5 kernels)
    k_init_deg<<<(NN + 255) / 256, 256>>>();
    k_count_deg<<<(NE + 255) / 256, 256>>>(ei);
    k_scan_blocks<<<(NN + 1023) / 1024, 1024>>>();
    k_add_off<<<(NN + 255) / 256, 256>>>();
    k_fill_col<<<(NEP + 255) / 256, 256>>>(ei);

    // ---- layer 0 (fully algebraic; X0 and its logits never materialized) ----
    k_w0_table<<<201, 512>>>(embt, W0, db, dw);
    k_alphas<<<201, 128>>>(pT, as0, ad0, pTAs, pTAd);
    k_gather0<<<(NN + 3) / 4, 512>>>(x, depth, b0, pO);
    k_bn_stats_final<<<128, 512>>>(pO, 512, g0, be0, 0);
    k_bn_elu_split<<<(NN * 128 + 255) / 256, 256>>>((const float4*)pO,
        (__nv_bfloat162*)pAh, (__nv_bfloat162*)pAl, NN * 128, 127);

    // ---- layer 1: 512 -> 4x128 concat ----
    k_cvt_split4<<<(512 * 128 + 255) / 256, 256>>>((const float4*)W1, (__nv_bfloat162*)pBh, (__nv_bfloat162*)pBl, 512 * 128);
    k_mma_gemm<<<dim3(4, MB), 256, GEMM_SMEM>>>(pAh, pAl, pBh, pBl, pX16, NN, 512, 512, as1, ad1);
    k_gather4<<<(NN + 3) / 4, 512>>>(pX16, b1, pO);
    k_bn_stats_final<<<128, 512>>>(pO, 512, g1, be1, 1);
    k_bn_elu_split<<<(NN * 128 + 255) / 256, 256>>>((const float4*)pO,
        (__nv_bfloat162*)pAh, (__nv_bfloat162*)pAl, NN * 128, 127);

    // ---- layer 2: 512 -> 128, 1 head ----
    k_cvt_split4<<<(128 * 128 + 255) / 256, 256>>>((const float4*)W2, (__nv_bfloat162*)pBh, (__nv_bfloat162*)pBl, 128 * 128);
    k_mma_gemm<<<dim3(1, MB), 256, GEMM_SMEM>>>(pAh, pAl, pBh, pBl, pX16, NN, 128, 512, as2, ad2);
    k_gather1<<<(NN + 15) / 16, 512>>>(pX16, b2, pO);
    k_bn_stats_final<<<128, 128>>>(pO, 128, g2, be2, 2);   // also inits pooling arrays

    // ---- pooling (fused BN+ELU+counts) + classifier ----
    k_pool_bn<<<(NN + 255) / 256, 128>>>(pO, batch);
    k_classifier<<<NG, 256>>>(cw1, cb1, cw2, cb2, out);
}

// round 15
// speedup vs baseline: 1.0634x; 1.0634x over previous
#include <cuda_runtime.h>
#include <cuda_bf16.h>
#include <cuda_fp16.h>
#include <math.h>
#include <cstdint>

#define NN 50000
#define NE 400000
#define NEP 450000        // edges + self loops
#define NG 256
#define FMAXC 512
#define BN_EPS 1e-5f
#define NEG 0.2f

// ---------------- scratch (device globals; no allocations) ----------------
__device__ __half g_X16[(size_t)NN * FMAXC];  // projected features (fp16)
__device__ float g_O[(size_t)NN * FMAXC];     // aggregated output (pre-BN)
__device__ __nv_bfloat16 g_Ah[(size_t)NN * FMAXC];
__device__ __nv_bfloat16 g_Al[(size_t)NN * FMAXC];
__device__ __nv_bfloat16 g_Bh[FMAXC * FMAXC];
__device__ __nv_bfloat16 g_Bl[FMAXC * FMAXC];
__device__ float g_T[201 * 512];            // row 200 = dvec (fp32, for logits & dv)
__device__ __half g_T16[201 * 512];         // fp16 copy for gather
__device__ float g_TAs[201 * 4];
__device__ float g_TAd[201 * 4];
__device__ float g_als[NN * 4];
__device__ float g_ald[NN * 4];
__device__ int   g_deg[NN];
__device__ int   g_rowptr[NN + 1];
__device__ int   g_cursor[NN];
__device__ int   g_col[NEP];
__device__ int   g_part[64];
__device__ float g_psums[128 * FMAXC];
__device__ float g_psumsq[128 * FMAXC];
__device__ float g_scale[FMAXC];
__device__ float g_shift[FMAXC];
__device__ int   g_bn_ctr[4];               // zero-initialized; self-resetting
__device__ float g_psum[NG * 128];
__device__ unsigned g_pmax[NG * 128];
__device__ int   g_count[NG];

__device__ __forceinline__ float leaky(float x) { return x >= 0.f ? x : NEG * x; }

__device__ __forceinline__ unsigned enc_f(float f) {
    unsigned u = __float_as_uint(f);
    return (u & 0x80000000u) ? ~u : (u | 0x80000000u);
}
__device__ __forceinline__ float dec_f(unsigned u) {
    return (u & 0x80000000u) ? __uint_as_float(u & 0x7fffffffu) : __uint_as_float(~u);
}

// ---------------- cp.async / mma / ldmatrix helpers (baseline PTX) ----------------
__device__ __forceinline__ uint32_t smem_u32(const void* p) {
    uint32_t a;
    asm("{ .reg .u64 t; cvta.to.shared.u64 t, %1; cvt.u32.u64 %0, t; }" : "=r"(a) : "l"(p));
    return a;
}
__device__ __forceinline__ void cp16(uint32_t dst, const void* src) {
    asm volatile("cp.async.cg.shared.global [%0], [%1], 16;" :: "r"(dst), "l"(src));
}
#define CP_COMMIT() asm volatile("cp.async.commit_group;" ::: "memory")
#define CP_WAIT1()  asm volatile("cp.async.wait_group 1;" ::: "memory")
#define CP_WAIT0()  asm volatile("cp.async.wait_group 0;" ::: "memory")

__device__ __forceinline__ void mma16816(float* c, const uint32_t* a, const uint32_t* b) {
    asm volatile(
        "mma.sync.aligned.m16n8k16.row.col.f32.bf16.bf16.f32 "
        "{%0,%1,%2,%3}, {%4,%5,%6,%7}, {%8,%9}, {%0,%1,%2,%3};"
        : "+f"(c[0]), "+f"(c[1]), "+f"(c[2]), "+f"(c[3])
        : "r"(a[0]), "r"(a[1]), "r"(a[2]), "r"(a[3]), "r"(b[0]), "r"(b[1]));
}
__device__ __forceinline__ void ldsm_x4(uint32_t* r, uint32_t addr) {
    asm volatile("ldmatrix.sync.aligned.m8n8.x4.shared.b16 {%0,%1,%2,%3}, [%4];"
                 : "=r"(r[0]), "=r"(r[1]), "=r"(r[2]), "=r"(r[3]) : "r"(addr));
}
__device__ __forceinline__ void ldsm_x2(uint32_t* r, uint32_t addr) {
    asm volatile("ldmatrix.sync.aligned.m8n8.x2.shared.b16 {%0,%1}, [%2];"
                 : "=r"(r[0]), "=r"(r[1]) : "r"(addr));
}

// ---------------- fp32 -> bf16 hi/lo split conversion (vectorized) ----------------
__global__ void k_cvt_split4(const float4* __restrict__ src, __nv_bfloat162* __restrict__ hi,
                             __nv_bfloat162* __restrict__ lo, int total4) {
    int i = blockIdx.x * blockDim.x + threadIdx.x;
    if (i < total4) {
        float4 v = src[i];
        __nv_bfloat16 hx = __float2bfloat16(v.x), hy = __float2bfloat16(v.y);
        __nv_bfloat16 hz = __float2bfloat16(v.z), hw = __float2bfloat16(v.w);
        hi[2 * i]     = __nv_bfloat162(hx, hy);
        hi[2 * i + 1] = __nv_bfloat162(hz, hw);
        lo[2 * i]     = __nv_bfloat162(__float2bfloat16(v.x - __bfloat162float(hx)),
                                       __float2bfloat16(v.y - __bfloat162float(hy)));
        lo[2 * i + 1] = __nv_bfloat162(__float2bfloat16(v.z - __bfloat162float(hz)),
                                       __float2bfloat16(v.w - __bfloat162float(hw)));
    }
}

// ---------------- layer-0 algebraic tables (T rows 0..199 = types, 200 = dvec) ----
__global__ void __launch_bounds__(512) k_w0_table(const float* __restrict__ emb,
                                                  const float* __restrict__ W0,
                                                  const float* __restrict__ db,
                                                  const float* __restrict__ dw) {
    __shared__ float er[64];
    int r = blockIdx.x, c = threadIdx.x;
    if (c < 64) er[c] = (r < 200) ? (emb[r * 64 + c] + db[c]) : dw[c];
    __syncthreads();
    const float* w = W0 + c * 64;
    float s = 0.f;
#pragma unroll 16
    for (int k = 0; k < 64; ++k) s += er[k] * w[k];
    g_T[r * 512 + c] = s;
    g_T16[r * 512 + c] = __float2half(s);
}
// per-row logits of T (incl. dvec row): outS/outD [201,4]
__global__ void k_alphas(const float* __restrict__ Xp, const float* __restrict__ asrc,
                         const float* __restrict__ adst,
                         float* __restrict__ outS, float* __restrict__ outD) {
    int n = blockIdx.x;
    int w = threadIdx.x >> 5, lane = threadIdx.x & 31;
    const float* xr = Xp + (size_t)n * 512 + w * 128;
    float ss = 0.f, sd = 0.f;
#pragma unroll
    for (int j = 0; j < 4; j++) {
        float v = xr[lane + 32 * j];
        ss += v * asrc[w * 128 + lane + 32 * j];
        sd += v * adst[w * 128 + lane + 32 * j];
    }
#pragma unroll
    for (int off = 16; off; off >>= 1) {
        ss += __shfl_down_sync(0xffffffffu, ss, off);
        sd += __shfl_down_sync(0xffffffffu, sd, off);
    }
    if (lane == 0) { outS[n * 4 + w] = ss; outD[n * 4 + w] = sd; }
}

// ---------- fused gathers: per-node 128-thread block; warp h = head h ----------
__global__ void __launch_bounds__(128)
k_gather4(const __half* __restrict__ Xp, const float* __restrict__ bias,
          float* __restrict__ out) {
    int n = blockIdx.x;
    int h = threadIdx.x >> 5, l = threadIdx.x & 31;
    int beg = g_rowptr[n], end = g_rowptr[n + 1];
    float ald_n = g_ald[n * 4 + h];
    int off = h * 128 + l * 4;
    float4 acc = make_float4(0.f, 0.f, 0.f, 0.f);
    float wsum = 0.f;
    for (int base = beg; base < end; base += 32) {
        int cnt = min(32, end - base);
        float w = 0.f; int s = 0;
        if (l < cnt) {
            s = g_col[base + l];
            w = __expf(leaky(g_als[s * 4 + h] + ald_n));
        }
        wsum += w;
        for (int j = 0; j < cnt; ++j) {
            float wj = __shfl_sync(0xffffffffu, w, j);
            int   sj = __shfl_sync(0xffffffffu, s, j);
            uint2 hv = *(const uint2*)(Xp + (size_t)sj * 512 + off);
            float2 f0 = __half22float2(*(__half2*)&hv.x);
            float2 f1 = __half22float2(*(__half2*)&hv.y);
            acc.x += wj * f0.x; acc.y += wj * f0.y;
            acc.z += wj * f1.x; acc.w += wj * f1.y;
        }
    }
#pragma unroll
    for (int o = 16; o; o >>= 1) wsum += __shfl_xor_sync(0xffffffffu, wsum, o);
    float inv = 1.f / wsum;
    float4 bv = *(const float4*)(bias + off);
    *(float4*)(out + (size_t)n * 512 + off) =
        make_float4(acc.x * inv + bv.x, acc.y * inv + bv.y,
                    acc.z * inv + bv.z, acc.w * inv + bv.w);
}

// layer-0: rows AND logits reconstructed from T16/TAs/TAd (all cache-resident)
__global__ void __launch_bounds__(128)
k_gather0(const int* __restrict__ x, const float* __restrict__ depth,
          const float* __restrict__ bias, float* __restrict__ out) {
    int n = blockIdx.x;
    int h = threadIdx.x >> 5, l = threadIdx.x & 31;
    int beg = g_rowptr[n], end = g_rowptr[n + 1];
    int xt_n = __ldg(&x[n]);
    float d_n = __ldg(&depth[n]);
    float ald_n = g_TAd[xt_n * 4 + h] + d_n * g_TAd[200 * 4 + h];
    float tas_dv = g_TAs[200 * 4 + h];
    int off = h * 128 + l * 4;
    float4 dv = *(const float4*)(g_T + 200 * 512 + off);
    float4 acc = make_float4(0.f, 0.f, 0.f, 0.f);
    float wsum = 0.f;
    for (int base = beg; base < end; base += 32) {
        int cnt = min(32, end - base);
        float w = 0.f; int xt = 0; float d = 0.f;
        if (l < cnt) {
            int s = g_col[base + l];
            xt = __ldg(&x[s]);
            d  = __ldg(&depth[s]);
            float als_s = g_TAs[xt * 4 + h] + d * tas_dv;
            w  = __expf(leaky(als_s + ald_n));
        }
        wsum += w;
        for (int j = 0; j < cnt; ++j) {
            float wj = __shfl_sync(0xffffffffu, w, j);
            int   xj = __shfl_sync(0xffffffffu, xt, j);
            float dj = __shfl_sync(0xffffffffu, d, j);
            uint2 hv = *(const uint2*)(g_T16 + xj * 512 + off);
            float2 f0 = __half22float2(*(__half2*)&hv.x);
            float2 f1 = __half22float2(*(__half2*)&hv.y);
            acc.x += wj * (f0.x + dj * dv.x);
            acc.y += wj * (f0.y + dj * dv.y);
            acc.z += wj * (f1.x + dj * dv.z);
            acc.w += wj * (f1.y + dj * dv.w);
        }
    }
#pragma unroll
    for (int o = 16; o; o >>= 1) wsum += __shfl_xor_sync(0xffffffffu, wsum, o);
    float inv = 1.f / wsum;
    float4 bv = *(const float4*)(bias + off);
    *(float4*)(out + (size_t)n * 512 + off) =
        make_float4(acc.x * inv + bv.x, acc.y * inv + bv.y,
                    acc.z * inv + bv.z, acc.w * inv + bv.w);
}

// H=1: 4 nodes/block (128 thr), warp per node; als/ald dense; fp16 X
__global__ void __launch_bounds__(128)
k_gather1(const __half* __restrict__ Xp, const float* __restrict__ bias,
          float* __restrict__ out) {
    int wp = threadIdx.x >> 5, l = threadIdx.x & 31;
    int n = blockIdx.x * 4 + wp;
    if (n >= NN) return;
    int beg = g_rowptr[n], end = g_rowptr[n + 1];
    float ald_n = g_ald[n];
    float4 acc = make_float4(0.f, 0.f, 0.f, 0.f);
    float wsum = 0.f;
    for (int base = beg; base < end; base += 32) {
        int cnt = min(32, end - base);
        float w = 0.f; int s = 0;
        if (l < cnt) {
            s = g_col[base + l];
            w = __expf(leaky(g_als[s] + ald_n));
        }
        wsum += w;
        for (int j = 0; j < cnt; ++j) {
            float wj = __shfl_sync(0xffffffffu, w, j);
            int   sj = __shfl_sync(0xffffffffu, s, j);
            uint2 hv = *(const uint2*)(Xp + (size_t)sj * 128 + l * 4);
            float2 f0 = __half22float2(*(__half2*)&hv.x);
            float2 f1 = __half22float2(*(__half2*)&hv.y);
            acc.x += wj * f0.x; acc.y += wj * f0.y;
            acc.z += wj * f1.x; acc.w += wj * f1.y;
        }
    }
#pragma unroll
    for (int o = 16; o; o >>= 1) wsum += __shfl_xor_sync(0xffffffffu, wsum, o);
    float inv = 1.f / wsum;
    float4 bv = *(const float4*)(bias + l * 4);
    *(float4*)(out + (size_t)n * 128 + l * 4) =
        make_float4(acc.x * inv + bv.x, acc.y * inv + bv.y,
                    acc.z * inv + bv.z, acc.w * inv + bv.w);
}

// ---------------- HMMA GEMM: fp16 C store + fused attention logits ----------------
#define TILE_E 5120          // 128*40 elements per tile
#define STAGE_E (4 * TILE_E) // Ah,Al,Bh,Bl
#define GEMM_SMEM (2 * STAGE_E * 2)
__global__ void __launch_bounds__(256)
k_mma_gemm(const __nv_bfloat16* __restrict__ Ah, const __nv_bfloat16* __restrict__ Al,
           const __nv_bfloat16* __restrict__ Bh, const __nv_bfloat16* __restrict__ Bl,
           __half* __restrict__ C, int M, int N, int K,
           const float* __restrict__ av_s, const float* __restrict__ av_d) {
    extern __shared__ __nv_bfloat16 smem[];
    const int tid = threadIdx.x;
    const int wid = tid >> 5, lane = tid & 31;
    const int gid = lane >> 2, tig = lane & 3;
    const int wr = wid & 3, wc = wid >> 2;
    const int brow = blockIdx.y * 128;
    const int bcol = blockIdx.x * 128;
    const uint32_t sbase = smem_u32(smem);

    const int nc = K >> 5;

    auto load_chunk = [&](int c, int stage) {
        int k0 = c << 5;
        uint32_t sb = sbase + stage * (STAGE_E * 2);
#pragma unroll
        for (int jj = 0; jj < 2; ++jj) {
            int j = tid * 2 + jj;
            int row = j >> 2, kk = j & 3;
            uint32_t doff = (uint32_t)(row * 80 + kk * 16);
            int gm = brow + row; if (gm >= M) gm = M - 1;
            size_t sa = (size_t)gm * K + k0 + kk * 8;
            cp16(sb + doff,              Ah + sa);
            cp16(sb + TILE_E * 2 + doff, Al + sa);
            size_t sbb = (size_t)(bcol + row) * K + k0 + kk * 8;
            cp16(sb + TILE_E * 4 + doff, Bh + sbb);
            cp16(sb + TILE_E * 6 + doff, Bl + sbb);
        }
    };

    float acc[2][8][4];
#pragma unroll
    for (int mt = 0; mt < 2; ++mt)
#pragma unroll
        for (int nt = 0; nt < 8; ++nt)
#pragma unroll
            for (int q = 0; q < 4; ++q) acc[mt][nt][q] = 0.f;

    const uint32_t aoff = (uint32_t)((lane & 15) * 80 + (lane >> 4) * 16);
    const uint32_t boff = (uint32_t)((lane & 7) * 80 + ((lane >> 3) & 1) * 16);

    load_chunk(0, 0); CP_COMMIT();
    load_chunk(1, 1); CP_COMMIT();

    for (int c = 0; c < nc; ++c) {
        if (c < nc - 1) { CP_WAIT1(); } else { CP_WAIT0(); }
        __syncthreads();
        uint32_t stB = sbase + (c & 1) * (STAGE_E * 2);
        uint32_t aA  = stB + (uint32_t)(32 * wr * 80) + aoff;
        uint32_t aAl = aA + TILE_E * 2;
        uint32_t aB  = stB + TILE_E * 4 + (uint32_t)(64 * wc * 80) + boff;
        uint32_t aBl = aB + TILE_E * 2;
#pragma unroll
        for (int ks = 0; ks < 2; ++ks) {
            const uint32_t kb = ks * 32;
            uint32_t ah[2][4], al[2][4];
#pragma unroll
            for (int mt = 0; mt < 2; ++mt) {
                ldsm_x4(ah[mt], aA  + mt * (16 * 80) + kb);
                ldsm_x4(al[mt], aAl + mt * (16 * 80) + kb);
            }
#pragma unroll
            for (int nt = 0; nt < 8; ++nt) {
                uint32_t bh[2], bl[2];
                ldsm_x2(bh, aB  + nt * (8 * 80) + kb);
                ldsm_x2(bl, aBl + nt * (8 * 80) + kb);
#pragma unroll
                for (int mt = 0; mt < 2; ++mt) {
                    mma16816(acc[mt][nt], ah[mt], bh);
                    mma16816(acc[mt][nt], ah[mt], bl);
                    mma16816(acc[mt][nt], al[mt], bh);
                }
            }
        }
        __syncthreads();
        if (c + 2 < nc) { load_chunk(c + 2, c & 1); CP_COMMIT(); }
    }

    // store C (fp16)
#pragma unroll
    for (int mt = 0; mt < 2; ++mt) {
        int r0 = brow + 32 * wr + 16 * mt + gid;
#pragma unroll
        for (int nt = 0; nt < 8; ++nt) {
            int n0 = bcol + 64 * wc + 8 * nt + tig * 2;
            if (r0 < M)
                *(__half2*)(C + (size_t)r0 * N + n0) =
                    __floats2half2_rn(acc[mt][nt][0], acc[mt][nt][1]);
            if (r0 + 8 < M)
                *(__half2*)(C + (size_t)(r0 + 8) * N + n0) =
                    __floats2half2_rn(acc[mt][nt][2], acc[mt][nt][3]);
        }
    }

    // fused attention logits: als[r,h] = sum_col C[r,col]*av_s[col] (head = bcol/128)
    if (av_s) {
        const int HH = N >> 7;
        const int hh = bcol >> 7;
        float pa[2][2] = {{0.f, 0.f}, {0.f, 0.f}};
        float pd[2][2] = {{0.f, 0.f}, {0.f, 0.f}};
#pragma unroll
        for (int nt = 0; nt < 8; ++nt) {
            int lc = bcol + 64 * wc + 8 * nt + tig * 2;
            float as0 = __ldg(&av_s[lc]), as1 = __ldg(&av_s[lc + 1]);
            float ad0 = __ldg(&av_d[lc]), ad1 = __ldg(&av_d[lc + 1]);
#pragma unroll
            for (int mt = 0; mt < 2; ++mt) {
                pa[mt][0] += acc[mt][nt][0] * as0 + acc[mt][nt][1] * as1;
                pa[mt][1] += acc[mt][nt][2] * as0 + acc[mt][nt][3] * as1;
                pd[mt][0] += acc[mt][nt][0] * ad0 + acc[mt][nt][1] * ad1;
                pd[mt][1] += acc[mt][nt][2] * ad0 + acc[mt][nt][3] * ad1;
            }
        }
        float* sa = (float*)smem;        // [2][128]
        float* sd = sa + 256;            // [2][128]
#pragma unroll
        for (int mt = 0; mt < 2; ++mt)
#pragma unroll
            for (int rh = 0; rh < 2; ++rh) {
                float va = pa[mt][rh], vd = pd[mt][rh];
                va += __shfl_xor_sync(0xffffffffu, va, 1);
                va += __shfl_xor_sync(0xffffffffu, va, 2);
                vd += __shfl_xor_sync(0xffffffffu, vd, 1);
                vd += __shfl_xor_sync(0xffffffffu, vd, 2);
                if (tig == 0) {
                    int rl = 32 * wr + 16 * mt + 8 * rh + gid;
                    sa[wc * 128 + rl] = va;
                    sd[wc * 128 + rl] = vd;
                }
            }
        __syncthreads();
        if (tid < 128) {
            int r = brow + tid;
            if (r < M) {
                g_als[r * HH + hh] = sa[tid] + sa[128 + tid];
                g_ald[r * HH + hh] = sd[tid] + sd[128 + tid];
            }
        }
    }
}

// ---------------- graph build (CSR by dst, incl. self loops) ----------------
__global__ void k_init_deg() {
    int i = blockIdx.x * blockDim.x + threadIdx.x;
    if (i < NN) g_deg[i] = 1;
}
__global__ void k_count_deg(const int* __restrict__ ei) {
    int e = blockIdx.x * blockDim.x + threadIdx.x;
    if (e < NE) atomicAdd(&g_deg[ei[NE + e]], 1);
}
__global__ void k_scan_blocks() {
    __shared__ int s[1024];
    int t = threadIdx.x;
    int i = blockIdx.x * 1024 + t;
    int v = (i < NN) ? g_deg[i] : 0;
    s[t] = v;
    __syncthreads();
    for (int off = 1; off < 1024; off <<= 1) {
        int add = (t >= off) ? s[t - off] : 0;
        __syncthreads();
        s[t] += add;
        __syncthreads();
    }
    if (i < NN) g_rowptr[i] = s[t] - v;
    if (t == 1023) g_part[blockIdx.x] = s[t];
}
// add chunk offsets (prefix of g_part computed redundantly per thread — 49 hot values)
__global__ void k_add_off() {
    int i = blockIdx.x * blockDim.x + threadIdx.x;
    if (i < NN) {
        int chunk = i >> 10;
        int off = 0;
        for (int c = 0; c < chunk; ++c) off += g_part[c];
        int r = g_rowptr[i] + off;
        g_rowptr[i] = r;
        g_cursor[i] = r;
    }
    if (i == 0) g_rowptr[NN] = NEP;
}
__global__ void k_fill_col(const int* __restrict__ ei) {
    int e = blockIdx.x * blockDim.x + threadIdx.x;
    if (e < NEP) {
        int s, d;
        if (e < NE) { s = ei[e]; d = ei[NE + e]; }
        else        { s = d = e - NE; }
        int pos = atomicAdd(&g_cursor[d], 1);
        g_col[pos] = s;
    }
}

// -------- batchnorm: partial sums + last-block final reduction (1 launch) --------
// which==2 additionally initializes the pooling arrays (pool_bn runs in a later kernel).
__global__ void k_bn_stats_final(const float* __restrict__ X, int F,
                                 const float* __restrict__ gam,
                                 const float* __restrict__ bet, int which) {
    int t = threadIdx.x, b = blockIdx.x;
    if (which == 2) {
        int gi = b * blockDim.x + t;          // 128*128 = 16384 threads
        g_psum[gi] = 0.f;              g_psum[gi + 16384] = 0.f;
        g_pmax[gi] = 0x00800000u;      g_pmax[gi + 16384] = 0x00800000u;
        if (gi < NG) g_count[gi] = 0;
    }
    const int rpb = (NN + 127) / 128;
    int r0 = b * rpb;
    int r1 = r0 + rpb; if (r1 > NN) r1 = NN;
    float s = 0.f, s2 = 0.f;
    for (int r = r0; r < r1; ++r) {
        float v = X[(size_t)r * F + t];
        s += v; s2 += v * v;
    }
    g_psums[b * F + t] = s;
    g_psumsq[b * F + t] = s2;
    __threadfence();
    __shared__ int lastFlag;
    if (t == 0) lastFlag = (atomicAdd(&g_bn_ctr[which], 1) == 127) ? 1 : 0;
    __syncthreads();
    if (lastFlag) {
        float ss = 0.f, ss2 = 0.f;
        for (int bb = 0; bb < 128; ++bb) {
            ss += g_psums[bb * F + t];
            ss2 += g_psumsq[bb * F + t];
        }
        float m = ss * (1.f / NN);
        float var = ss2 * (1.f / NN) - m * m;
        float sc = gam[t] * rsqrtf(var + BN_EPS);
        g_scale[t] = sc;
        g_shift[t] = bet[t] - m * sc;
        if (t == 0) g_bn_ctr[which] = 0;   // self-reset
    }
}
__global__ void k_bn_elu_split(const float4* __restrict__ X, __nv_bfloat162* __restrict__ hi,
                               __nv_bfloat162* __restrict__ lo, int total4, int fmask4) {
    int i = blockIdx.x * blockDim.x + threadIdx.x;
    if (i < total4) {
        int c4 = (i & fmask4) << 2;
        float4 v = X[i];
        float4 sc = *(const float4*)&g_scale[c4];
        float4 sh = *(const float4*)&g_shift[c4];
        float a = fmaf(v.x, sc.x, sh.x); a = a > 0.f ? a : expm1f(a);
        float b = fmaf(v.y, sc.y, sh.y); b = b > 0.f ? b : expm1f(b);
        float cc = fmaf(v.z, sc.z, sh.z); cc = cc > 0.f ? cc : expm1f(cc);
        float d = fmaf(v.w, sc.w, sh.w); d = d > 0.f ? d : expm1f(d);
        __nv_bfloat16 ha = __float2bfloat16(a), hb = __float2bfloat16(b);
        __nv_bfloat16 hc = __float2bfloat16(cc), hd = __float2bfloat16(d);
        hi[2 * i]     = __nv_bfloat162(ha, hb);
        hi[2 * i + 1] = __nv_bfloat162(hc, hd);
        lo[2 * i]     = __nv_bfloat162(__float2bfloat16(a - __bfloat162float(ha)),
                                       __float2bfloat16(b - __bfloat162float(hb)));
        lo[2 * i + 1] = __nv_bfloat162(__float2bfloat16(cc - __bfloat162float(hc)),
                                       __float2bfloat16(d - __bfloat162float(hd)));
    }
}

// ---------------- pooling (fused final BN+ELU + graph counts) ----------------
__global__ void __launch_bounds__(128)
k_pool_bn(const float* __restrict__ X, const int* __restrict__ batch) {
    int t = threadIdx.x;
    float sc = g_scale[t], sh = g_shift[t];
    int r0 = blockIdx.x * 256;
    int r1 = r0 + 256; if (r1 > NN) r1 = NN;
    if (r0 >= NN) return;
    int cur = batch[r0];
    float s = 0.f, m = -3.4e38f;
    int runlen = 0;
    for (int r = r0; r < r1; ++r) {
        int g = batch[r];
        if (g != cur) {
            atomicAdd(&g_psum[cur * 128 + t], s);
            atomicMax(&g_pmax[cur * 128 + t], enc_f(m));
            if (t == 0) atomicAdd(&g_count[cur], runlen);
            s = 0.f; m = -3.4e38f; cur = g; runlen = 0;
        }
        float v = X[(size_t)r * 128 + t] * sc + sh;
        v = v > 0.f ? v : expm1f(v);
        s += v; m = fmaxf(m, v);
        ++runlen;
    }
    atomicAdd(&g_psum[cur * 128 + t], s);
    atomicMax(&g_pmax[cur * 128 + t], enc_f(m));
    if (t == 0) atomicAdd(&g_count[cur], runlen);
}

// ---------------- classifier ----------------
__global__ void __launch_bounds__(256)
k_classifier(const float* __restrict__ cw1, const float* __restrict__ cb1,
             const float* __restrict__ cw2, const float* __restrict__ cb2,
             float* __restrict__ out) {
    __shared__ float s_emb[256];
    __shared__ float s_hid[256];
    int g = blockIdx.x, t = threadIdx.x;
    if (t < 128) {
        float c = (float)g_count[g];
        c = fmaxf(c, 1.f);
        s_emb[t] = g_psum[g * 128 + t] / c;
        s_emb[128 + t] = dec_f(g_pmax[g * 128 + t]);
    }
    __syncthreads();
    float a = cb1[t];
    const float* wr = cw1 + (size_t)t * 256;
    for (int j = 0; j < 256; j++) a += s_emb[j] * wr[j];
    s_hid[t] = fmaxf(a, 0.f);
    __syncthreads();
    if (t < 20) {
        float o = cb2[t];
        const float* w2 = cw2 + (size_t)t * 256;
        for (int j = 0; j < 256; j++) o += s_hid[j] * w2[j];
        out[g * 20 + t] = o;
    }
}

// ---------------- launch ----------------
extern "C" void kernel_launch(void* const* d_in, const int* in_sizes, int n_in,
                              void* d_out, int out_size) {
    const int*   x     = (const int*)d_in[0];
    const int*   ei    = (const int*)d_in[1];
    const float* depth = (const float*)d_in[2];
    const int*   batch = (const int*)d_in[3];
    const float* embt  = (const float*)d_in[4];
    const float* dw    = (const float*)d_in[5];
    const float* db    = (const float*)d_in[6];
    const float* W0  = (const float*)d_in[7];
    const float* as0 = (const float*)d_in[8];
    const float* ad0 = (const float*)d_in[9];
    const float* b0  = (const float*)d_in[10];
    const float* g0  = (const float*)d_in[11];
    const float* be0 = (const float*)d_in[12];
    const float* W1  = (const float*)d_in[13];
    const float* as1 = (const float*)d_in[14];
    const float* ad1 = (const float*)d_in[15];
    const float* b1  = (const float*)d_in[16];
    const float* g1  = (const float*)d_in[17];
    const float* be1 = (const float*)d_in[18];
    const float* W2  = (const float*)d_in[19];
    const float* as2 = (const float*)d_in[20];
    const float* ad2 = (const float*)d_in[21];
    const float* b2  = (const float*)d_in[22];
    const float* g2  = (const float*)d_in[23];
    const float* be2 = (const float*)d_in[24];
    const float* cw1 = (const float*)d_in[25];
    const float* cb1 = (const float*)d_in[26];
    const float* cw2 = (const float*)d_in[27];
    const float* cb2 = (const float*)d_in[28];
    float* out = (float*)d_out;

    float *pO = nullptr, *pT = nullptr;
    float *pTAs = nullptr, *pTAd = nullptr;
    __half *pX16 = nullptr;
    __nv_bfloat16 *pAh = nullptr, *pAl = nullptr, *pBh = nullptr, *pBl = nullptr;
    cudaGetSymbolAddress((void**)&pX16, g_X16);
    cudaGetSymbolAddress((void**)&pO, g_O);
    cudaGetSymbolAddress((void**)&pT, g_T);
    cudaGetSymbolAddress((void**)&pTAs, g_TAs);
    cudaGetSymbolAddress((void**)&pTAd, g_TAd);
    cudaGetSymbolAddress((void**)&pAh, g_Ah);
    cudaGetSymbolAddress((void**)&pAl, g_Al);
    cudaGetSymbolAddress((void**)&pBh, g_Bh);
    cudaGetSymbolAddress((void**)&pBl, g_Bl);

    cudaFuncSetAttribute(k_mma_gemm, cudaFuncAttributeMaxDynamicSharedMemorySize, GEMM_SMEM);

    const int MB = (NN + 127) / 128;

    // CSR build (5 kernels)
    k_init_deg<<<(NN + 255) / 256, 256>>>();
    k_count_deg<<<(NE + 255) / 256, 256>>>(ei);
    k_scan_blocks<<<(NN + 1023) / 1024, 1024>>>();
    k_add_off<<<(NN + 255) / 256, 256>>>();
    k_fill_col<<<(NEP + 255) / 256, 256>>>(ei);

    // ---- layer 0 (fully algebraic; X0 and its logits never materialized) ----
    k_w0_table<<<201, 512>>>(embt, W0, db, dw);
    k_alphas<<<201, 128>>>(pT, as0, ad0, pTAs, pTAd);
    k_gather0<<<NN, 128>>>(x, depth, b0, pO);
    k_bn_stats_final<<<128, 512>>>(pO, 512, g0, be0, 0);
    k_bn_elu_split<<<(NN * 128 + 255) / 256, 256>>>((const float4*)pO,
        (__nv_bfloat162*)pAh, (__nv_bfloat162*)pAl, NN * 128, 127);

    // ---- layer 1: 512 -> 4x128 concat ----
    k_cvt_split4<<<(512 * 128 + 255) / 256, 256>>>((const float4*)W1, (__nv_bfloat162*)pBh, (__nv_bfloat162*)pBl, 512 * 128);
    k_mma_gemm<<<dim3(4, MB), 256, GEMM_SMEM>>>(pAh, pAl, pBh, pBl, pX16, NN, 512, 512, as1, ad1);
    k_gather4<<<NN, 128>>>(pX16, b1, pO);
    k_bn_stats_final<<<128, 512>>>(pO, 512, g1, be1, 1);
    k_bn_elu_split<<<(NN * 128 + 255) / 256, 256>>>((const float4*)pO,
        (__nv_bfloat162*)pAh, (__nv_bfloat162*)pAl, NN * 128, 127);

    // ---- layer 2: 512 -> 128, 1 head ----
    k_cvt_split4<<<(128 * 128 + 255) / 256, 256>>>((const float4*)W2, (__nv_bfloat162*)pBh, (__nv_bfloat162*)pBl, 128 * 128);
    k_mma_gemm<<<dim3(1, MB), 256, GEMM_SMEM>>>(pAh, pAl, pBh, pBl, pX16, NN, 128, 512, as2, ad2);
    k_gather1<<<(NN + 3) / 4, 128>>>(pX16, b2, pO);
    k_bn_stats_final<<<128, 128>>>(pO, 128, g2, be2, 2);   // also inits pooling arrays

    // ---- pooling (fused BN+ELU+counts) + classifier ----
    k_pool_bn<<<(NN + 255) / 256, 128>>>(pO, batch);
    k_classifier<<<NG, 256>>>(cw1, cb1, cw2, cb2, out);
}

// round 17
// speedup vs baseline: 1.0682x; 1.0045x over previous
#include <cuda_runtime.h>
#include <cuda_bf16.h>
#include <cuda_fp16.h>
#include <math.h>
#include <cstdint>

#define NN 50000
#define NE 400000
#define NEP 450000        // edges + self loops
#define NG 256
#define FMAXC 512
#define BN_EPS 1e-5f
#define NEG 0.2f

// ---------------- scratch (device globals; no allocations) ----------------
__device__ __half g_X16[(size_t)NN * FMAXC];  // projected features (fp16)
__device__ float g_O[(size_t)NN * FMAXC];     // aggregated output (pre-BN)
__device__ __nv_bfloat16 g_Ah[(size_t)NN * FMAXC];
__device__ __nv_bfloat16 g_Al[(size_t)NN * FMAXC];
__device__ __nv_bfloat16 g_Bh[FMAXC * FMAXC];
__device__ __nv_bfloat16 g_Bl[FMAXC * FMAXC];
__device__ float g_T[201 * 512];            // row 200 = dvec (fp32, for logits & dv)
__device__ __half g_T16[201 * 512];         // fp16 copy for gather
__device__ float g_TAs[201 * 4];
__device__ float g_TAd[201 * 4];
__device__ float g_als[NN * 4];
__device__ float g_ald[NN * 4];
__device__ int   g_deg[NN];
__device__ int   g_rowptr[NN + 1];
__device__ int   g_cursor[NN];
__device__ int   g_col[NEP];
__device__ int   g_part[64];
__device__ float g_psums[128 * FMAXC];
__device__ float g_psumsq[128 * FMAXC];
__device__ float g_scale[FMAXC];
__device__ float g_shift[FMAXC];
__device__ int   g_bn_ctr[4];               // zero-initialized; self-resetting
__device__ float g_psum[NG * 128];
__device__ unsigned g_pmax[NG * 128];
__device__ int   g_count[NG];

__device__ __forceinline__ float leaky(float x) { return x >= 0.f ? x : NEG * x; }

__device__ __forceinline__ unsigned enc_f(float f) {
    unsigned u = __float_as_uint(f);
    return (u & 0x80000000u) ? ~u : (u | 0x80000000u);
}
__device__ __forceinline__ float dec_f(unsigned u) {
    return (u & 0x80000000u) ? __uint_as_float(u & 0x7fffffffu) : __uint_as_float(~u);
}

// ---------------- cp.async / mma / ldmatrix helpers (baseline PTX) ----------------
__device__ __forceinline__ uint32_t smem_u32(const void* p) {
    uint32_t a;
    asm("{ .reg .u64 t; cvta.to.shared.u64 t, %1; cvt.u32.u64 %0, t; }" : "=r"(a) : "l"(p));
    return a;
}
__device__ __forceinline__ void cp16(uint32_t dst, const void* src) {
    asm volatile("cp.async.cg.shared.global [%0], [%1], 16;" :: "r"(dst), "l"(src));
}
#define CP_COMMIT() asm volatile("cp.async.commit_group;" ::: "memory")
#define CP_WAIT1()  asm volatile("cp.async.wait_group 1;" ::: "memory")
#define CP_WAIT0()  asm volatile("cp.async.wait_group 0;" ::: "memory")

__device__ __forceinline__ void mma16816(float* c, const uint32_t* a, const uint32_t* b) {
    asm volatile(
        "mma.sync.aligned.m16n8k16.row.col.f32.bf16.bf16.f32 "
        "{%0,%1,%2,%3}, {%4,%5,%6,%7}, {%8,%9}, {%0,%1,%2,%3};"
        : "+f"(c[0]), "+f"(c[1]), "+f"(c[2]), "+f"(c[3])
        : "r"(a[0]), "r"(a[1]), "r"(a[2]), "r"(a[3]), "r"(b[0]), "r"(b[1]));
}
__device__ __forceinline__ void ldsm_x4(uint32_t* r, uint32_t addr) {
    asm volatile("ldmatrix.sync.aligned.m8n8.x4.shared.b16 {%0,%1,%2,%3}, [%4];"
                 : "=r"(r[0]), "=r"(r[1]), "=r"(r[2]), "=r"(r[3]) : "r"(addr));
}
__device__ __forceinline__ void ldsm_x2(uint32_t* r, uint32_t addr) {
    asm volatile("ldmatrix.sync.aligned.m8n8.x2.shared.b16 {%0,%1}, [%2];"
                 : "=r"(r[0]), "=r"(r[1]) : "r"(addr));
}

// ---------------- fp32 -> bf16 hi/lo split conversion (vectorized) ----------------
__global__ void k_cvt_split4(const float4* __restrict__ src, __nv_bfloat162* __restrict__ hi,
                             __nv_bfloat162* __restrict__ lo, int total4) {
    int i = blockIdx.x * blockDim.x + threadIdx.x;
    if (i < total4) {
        float4 v = src[i];
        __nv_bfloat16 hx = __float2bfloat16(v.x), hy = __float2bfloat16(v.y);
        __nv_bfloat16 hz = __float2bfloat16(v.z), hw = __float2bfloat16(v.w);
        hi[2 * i]     = __nv_bfloat162(hx, hy);
        hi[2 * i + 1] = __nv_bfloat162(hz, hw);
        lo[2 * i]     = __nv_bfloat162(__float2bfloat16(v.x - __bfloat162float(hx)),
                                       __float2bfloat16(v.y - __bfloat162float(hy)));
        lo[2 * i + 1] = __nv_bfloat162(__float2bfloat16(v.z - __bfloat162float(hz)),
                                       __float2bfloat16(v.w - __bfloat162float(hw)));
    }
}

// -------- layer-0 tables: T rows 0..199 = types, 200 = dvec; fused row logits ----
__global__ void __launch_bounds__(512) k_w0_table(const float* __restrict__ emb,
                                                  const float* __restrict__ W0,
                                                  const float* __restrict__ db,
                                                  const float* __restrict__ dw,
                                                  const float* __restrict__ as0,
                                                  const float* __restrict__ ad0) {
    __shared__ float er[64];
    __shared__ float red[32];
    int r = blockIdx.x, c = threadIdx.x;
    if (c < 64) er[c] = (r < 200) ? (emb[r * 64 + c] + db[c]) : dw[c];
    __syncthreads();
    const float* w = W0 + c * 64;
    float s = 0.f;
#pragma unroll 16
    for (int k = 0; k < 64; ++k) s += er[k] * w[k];
    g_T[r * 512 + c] = s;
    g_T16[r * 512 + c] = __float2half(s);
    // fused row logits: TAs[r,h] = sum over head h's 128 channels of T[r,c]*as0[c]
    float ss = s * as0[c], sd = s * ad0[c];
#pragma unroll
    for (int o = 16; o; o >>= 1) {
        ss += __shfl_down_sync(0xffffffffu, ss, o);
        sd += __shfl_down_sync(0xffffffffu, sd, o);
    }
    int wid = c >> 5;
    if ((c & 31) == 0) { red[wid] = ss; red[16 + wid] = sd; }
    __syncthreads();
    if (c < 4) {
        float a = 0.f, d2 = 0.f;
#pragma unroll
        for (int i = 0; i < 4; ++i) { a += red[c * 4 + i]; d2 += red[16 + c * 4 + i]; }
        g_TAs[r * 4 + c] = a;
        g_TAd[r * 4 + c] = d2;
    }
}

// ---------- fused gathers: per-node 128-thread block; warp h = head h ----------
__global__ void __launch_bounds__(128)
k_gather4(const __half* __restrict__ Xp, const float* __restrict__ bias,
          float* __restrict__ out) {
    int n = blockIdx.x;
    int h = threadIdx.x >> 5, l = threadIdx.x & 31;
    int beg = g_rowptr[n], end = g_rowptr[n + 1];
    float ald_n = g_ald[n * 4 + h];
    int off = h * 128 + l * 4;
    float4 acc = make_float4(0.f, 0.f, 0.f, 0.f);
    float wsum = 0.f;
    for (int base = beg; base < end; base += 32) {
        int cnt = min(32, end - base);
        float w = 0.f; int s = 0;
        if (l < cnt) {
            s = g_col[base + l];
            w = __expf(leaky(g_als[s * 4 + h] + ald_n));
        }
        wsum += w;
        for (int j = 0; j < cnt; ++j) {
            float wj = __shfl_sync(0xffffffffu, w, j);
            int   sj = __shfl_sync(0xffffffffu, s, j);
            uint2 hv = *(const uint2*)(Xp + (size_t)sj * 512 + off);
            float2 f0 = __half22float2(*(__half2*)&hv.x);
            float2 f1 = __half22float2(*(__half2*)&hv.y);
            acc.x += wj * f0.x; acc.y += wj * f0.y;
            acc.z += wj * f1.x; acc.w += wj * f1.y;
        }
    }
#pragma unroll
    for (int o = 16; o; o >>= 1) wsum += __shfl_xor_sync(0xffffffffu, wsum, o);
    float inv = 1.f / wsum;
    float4 bv = *(const float4*)(bias + off);
    *(float4*)(out + (size_t)n * 512 + off) =
        make_float4(acc.x * inv + bv.x, acc.y * inv + bv.y,
                    acc.z * inv + bv.z, acc.w * inv + bv.w);
}

// layer-0: rows AND logits reconstructed from T16/TAs/TAd (all cache-resident)
__global__ void __launch_bounds__(128)
k_gather0(const int* __restrict__ x, const float* __restrict__ depth,
          const float* __restrict__ bias, float* __restrict__ out) {
    int n = blockIdx.x;
    int h = threadIdx.x >> 5, l = threadIdx.x & 31;
    int beg = g_rowptr[n], end = g_rowptr[n + 1];
    int xt_n = __ldg(&x[n]);
    float d_n = __ldg(&depth[n]);
    float ald_n = g_TAd[xt_n * 4 + h] + d_n * g_TAd[200 * 4 + h];
    float tas_dv = g_TAs[200 * 4 + h];
    int off = h * 128 + l * 4;
    float4 dv = *(const float4*)(g_T + 200 * 512 + off);
    float4 acc = make_float4(0.f, 0.f, 0.f, 0.f);
    float wsum = 0.f;
    for (int base = beg; base < end; base += 32) {
        int cnt = min(32, end - base);
        float w = 0.f; int xt = 0; float d = 0.f;
        if (l < cnt) {
            int s = g_col[base + l];
            xt = __ldg(&x[s]);
            d  = __ldg(&depth[s]);
            float als_s = g_TAs[xt * 4 + h] + d * tas_dv;
            w  = __expf(leaky(als_s + ald_n));
        }
        wsum += w;
        for (int j = 0; j < cnt; ++j) {
            float wj = __shfl_sync(0xffffffffu, w, j);
            int   xj = __shfl_sync(0xffffffffu, xt, j);
            float dj = __shfl_sync(0xffffffffu, d, j);
            uint2 hv = *(const uint2*)(g_T16 + xj * 512 + off);
            float2 f0 = __half22float2(*(__half2*)&hv.x);
            float2 f1 = __half22float2(*(__half2*)&hv.y);
            acc.x += wj * (f0.x + dj * dv.x);
            acc.y += wj * (f0.y + dj * dv.y);
            acc.z += wj * (f1.x + dj * dv.z);
            acc.w += wj * (f1.y + dj * dv.w);
        }
    }
#pragma unroll
    for (int o = 16; o; o >>= 1) wsum += __shfl_xor_sync(0xffffffffu, wsum, o);
    float inv = 1.f / wsum;
    float4 bv = *(const float4*)(bias + off);
    *(float4*)(out + (size_t)n * 512 + off) =
        make_float4(acc.x * inv + bv.x, acc.y * inv + bv.y,
                    acc.z * inv + bv.z, acc.w * inv + bv.w);
}

// H=1: 4 nodes/block (128 thr), warp per node; als/ald dense; fp16 X
__global__ void __launch_bounds__(128)
k_gather1(const __half* __restrict__ Xp, const float* __restrict__ bias,
          float* __restrict__ out) {
    int wp = threadIdx.x >> 5, l = threadIdx.x & 31;
    int n = blockIdx.x * 4 + wp;
    if (n >= NN) return;
    int beg = g_rowptr[n], end = g_rowptr[n + 1];
    float ald_n = g_ald[n];
    float4 acc = make_float4(0.f, 0.f, 0.f, 0.f);
    float wsum = 0.f;
    for (int base = beg; base < end; base += 32) {
        int cnt = min(32, end - base);
        float w = 0.f; int s = 0;
        if (l < cnt) {
            s = g_col[base + l];
            w = __expf(leaky(g_als[s] + ald_n));
        }
        wsum += w;
        for (int j = 0; j < cnt; ++j) {
            float wj = __shfl_sync(0xffffffffu, w, j);
            int   sj = __shfl_sync(0xffffffffu, s, j);
            uint2 hv = *(const uint2*)(Xp + (size_t)sj * 128 + l * 4);
            float2 f0 = __half22float2(*(__half2*)&hv.x);
            float2 f1 = __half22float2(*(__half2*)&hv.y);
            acc.x += wj * f0.x; acc.y += wj * f0.y;
            acc.z += wj * f1.x; acc.w += wj * f1.y;
        }
    }
#pragma unroll
    for (int o = 16; o; o >>= 1) wsum += __shfl_xor_sync(0xffffffffu, wsum, o);
    float inv = 1.f / wsum;
    float4 bv = *(const float4*)(bias + l * 4);
    *(float4*)(out + (size_t)n * 128 + l * 4) =
        make_float4(acc.x * inv + bv.x, acc.y * inv + bv.y,
                    acc.z * inv + bv.z, acc.w * inv + bv.w);
}

// ---------------- HMMA GEMM: fp16 C store + fused attention logits ----------------
#define TILE_E 5120          // 128*40 elements per tile
#define STAGE_E (4 * TILE_E) // Ah,Al,Bh,Bl
#define GEMM_SMEM (2 * STAGE_E * 2)
__global__ void __launch_bounds__(256)
k_mma_gemm(const __nv_bfloat16* __restrict__ Ah, const __nv_bfloat16* __restrict__ Al,
           const __nv_bfloat16* __restrict__ Bh, const __nv_bfloat16* __restrict__ Bl,
           __half* __restrict__ C, int M, int N, int K,
           const float* __restrict__ av_s, const float* __restrict__ av_d) {
    extern __shared__ __nv_bfloat16 smem[];
    const int tid = threadIdx.x;
    const int wid = tid >> 5, lane = tid & 31;
    const int gid = lane >> 2, tig = lane & 3;
    const int wr = wid & 3, wc = wid >> 2;
    const int brow = blockIdx.y * 128;
    const int bcol = blockIdx.x * 128;
    const uint32_t sbase = smem_u32(smem);

    const int nc = K >> 5;

    auto load_chunk = [&](int c, int stage) {
        int k0 = c << 5;
        uint32_t sb = sbase + stage * (STAGE_E * 2);
#pragma unroll
        for (int jj = 0; jj < 2; ++jj) {
            int j = tid * 2 + jj;
            int row = j >> 2, kk = j & 3;
            uint32_t doff = (uint32_t)(row * 80 + kk * 16);
            int gm = brow + row; if (gm >= M) gm = M - 1;
            size_t sa = (size_t)gm * K + k0 + kk * 8;
            cp16(sb + doff,              Ah + sa);
            cp16(sb + TILE_E * 2 + doff, Al + sa);
            size_t sbb = (size_t)(bcol + row) * K + k0 + kk * 8;
            cp16(sb + TILE_E * 4 + doff, Bh + sbb);
            cp16(sb + TILE_E * 6 + doff, Bl + sbb);
        }
    };

    float acc[2][8][4];
#pragma unroll
    for (int mt = 0; mt < 2; ++mt)
#pragma unroll
        for (int nt = 0; nt < 8; ++nt)
#pragma unroll
            for (int q = 0; q < 4; ++q) acc[mt][nt][q] = 0.f;

    const uint32_t aoff = (uint32_t)((lane & 15) * 80 + (lane >> 4) * 16);
    const uint32_t boff = (uint32_t)((lane & 7) * 80 + ((lane >> 3) & 1) * 16);

    load_chunk(0, 0); CP_COMMIT();
    load_chunk(1, 1); CP_COMMIT();

    for (int c = 0; c < nc; ++c) {
        if (c < nc - 1) { CP_WAIT1(); } else { CP_WAIT0(); }
        __syncthreads();
        uint32_t stB = sbase + (c & 1) * (STAGE_E * 2);
        uint32_t aA  = stB + (uint32_t)(32 * wr * 80) + aoff;
        uint32_t aAl = aA + TILE_E * 2;
        uint32_t aB  = stB + TILE_E * 4 + (uint32_t)(64 * wc * 80) + boff;
        uint32_t aBl = aB + TILE_E * 2;
#pragma unroll
        for (int ks = 0; ks < 2; ++ks) {
            const uint32_t kb = ks * 32;
            uint32_t ah[2][4], al[2][4];
#pragma unroll
            for (int mt = 0; mt < 2; ++mt) {
                ldsm_x4(ah[mt], aA  + mt * (16 * 80) + kb);
                ldsm_x4(al[mt], aAl + mt * (16 * 80) + kb);
            }
#pragma unroll
            for (int nt = 0; nt < 8; ++nt) {
                uint32_t bh[2], bl[2];
                ldsm_x2(bh, aB  + nt * (8 * 80) + kb);
                ldsm_x2(bl, aBl + nt * (8 * 80) + kb);
#pragma unroll
                for (int mt = 0; mt < 2; ++mt) {
                    mma16816(acc[mt][nt], ah[mt], bh);
                    mma16816(acc[mt][nt], ah[mt], bl);
                    mma16816(acc[mt][nt], al[mt], bh);
                }
            }
        }
        __syncthreads();
        if (c + 2 < nc) { load_chunk(c + 2, c & 1); CP_COMMIT(); }
    }

    // store C (fp16)
#pragma unroll
    for (int mt = 0; mt < 2; ++mt) {
        int r0 = brow + 32 * wr + 16 * mt + gid;
#pragma unroll
        for (int nt = 0; nt < 8; ++nt) {
            int n0 = bcol + 64 * wc + 8 * nt + tig * 2;
            if (r0 < M)
                *(__half2*)(C + (size_t)r0 * N + n0) =
                    __floats2half2_rn(acc[mt][nt][0], acc[mt][nt][1]);
            if (r0 + 8 < M)
                *(__half2*)(C + (size_t)(r0 + 8) * N + n0) =
                    __floats2half2_rn(acc[mt][nt][2], acc[mt][nt][3]);
        }
    }

    // fused attention logits: als[r,h] = sum_col C[r,col]*av_s[col] (head = bcol/128)
    if (av_s) {
        const int HH = N >> 7;
        const int hh = bcol >> 7;
        float pa[2][2] = {{0.f, 0.f}, {0.f, 0.f}};
        float pd[2][2] = {{0.f, 0.f}, {0.f, 0.f}};
#pragma unroll
        for (int nt = 0; nt < 8; ++nt) {
            int lc = bcol + 64 * wc + 8 * nt + tig * 2;
            float as0 = __ldg(&av_s[lc]), as1 = __ldg(&av_s[lc + 1]);
            float ad0 = __ldg(&av_d[lc]), ad1 = __ldg(&av_d[lc + 1]);
#pragma unroll
            for (int mt = 0; mt < 2; ++mt) {
                pa[mt][0] += acc[mt][nt][0] * as0 + acc[mt][nt][1] * as1;
                pa[mt][1] += acc[mt][nt][2] * as0 + acc[mt][nt][3] * as1;
                pd[mt][0] += acc[mt][nt][0] * ad0 + acc[mt][nt][1] * ad1;
                pd[mt][1] += acc[mt][nt][2] * ad0 + acc[mt][nt][3] * ad1;
            }
        }
        float* sa = (float*)smem;        // [2][128]
        float* sd = sa + 256;            // [2][128]
#pragma unroll
        for (int mt = 0; mt < 2; ++mt)
#pragma unroll
            for (int rh = 0; rh < 2; ++rh) {
                float va = pa[mt][rh], vd = pd[mt][rh];
                va += __shfl_xor_sync(0xffffffffu, va, 1);
                va += __shfl_xor_sync(0xffffffffu, va, 2);
                vd += __shfl_xor_sync(0xffffffffu, vd, 1);
                vd += __shfl_xor_sync(0xffffffffu, vd, 2);
                if (tig == 0) {
                    int rl = 32 * wr + 16 * mt + 8 * rh + gid;
                    sa[wc * 128 + rl] = va;
                    sd[wc * 128 + rl] = vd;
                }
            }
        __syncthreads();
        if (tid < 128) {
            int r = brow + tid;
            if (r < M) {
                g_als[r * HH + hh] = sa[tid] + sa[128 + tid];
                g_ald[r * HH + hh] = sd[tid] + sd[128 + tid];
            }
        }
    }
}

// ---------------- graph build (CSR by dst, incl. self loops) ----------------
__global__ void k_init_deg() {
    int i = blockIdx.x * blockDim.x + threadIdx.x;
    if (i < NN) g_deg[i] = 1;
}
__global__ void k_count_deg(const int* __restrict__ ei) {
    int e = blockIdx.x * blockDim.x + threadIdx.x;
    if (e < NE) atomicAdd(&g_deg[ei[NE + e]], 1);
}
__global__ void k_scan_blocks() {
    __shared__ int s[1024];
    int t = threadIdx.x;
    int i = blockIdx.x * 1024 + t;
    int v = (i < NN) ? g_deg[i] : 0;
    s[t] = v;
    __syncthreads();
    for (int off = 1; off < 1024; off <<= 1) {
        int add = (t >= off) ? s[t - off] : 0;
        __syncthreads();
        s[t] += add;
        __syncthreads();
    }
    if (i < NN) g_rowptr[i] = s[t] - v;
    if (t == 1023) g_part[blockIdx.x] = s[t];
}
__global__ void k_add_off() {
    int i = blockIdx.x * blockDim.x + threadIdx.x;
    if (i < NN) {
        int chunk = i >> 10;
        int off = 0;
        for (int c = 0; c < chunk; ++c) off += g_part[c];
        int r = g_rowptr[i] + off;
        g_rowptr[i] = r;
        g_cursor[i] = r;
    }
    if (i == 0) g_rowptr[NN] = NEP;
}
__global__ void k_fill_col(const int* __restrict__ ei) {
    int e = blockIdx.x * blockDim.x + threadIdx.x;
    if (e < NEP) {
        int s, d;
        if (e < NE) { s = ei[e]; d = ei[NE + e]; }
        else        { s = d = e - NE; }
        int pos = atomicAdd(&g_cursor[d], 1);
        g_col[pos] = s;
    }
}

// -------- batchnorm: partial sums + last-block final reduction (1 launch) --------
// which==2 additionally initializes the pooling arrays (pool_bn runs in a later kernel).
__global__ void k_bn_stats_final(const float* __restrict__ X, int F,
                                 const float* __restrict__ gam,
                                 const float* __restrict__ bet, int which) {
    int t = threadIdx.x, b = blockIdx.x;
    if (which == 2) {
        int gi = b * blockDim.x + t;          // 128*128 = 16384 threads
        g_psum[gi] = 0.f;              g_psum[gi + 16384] = 0.f;
        g_pmax[gi] = 0x00800000u;      g_pmax[gi + 16384] = 0x00800000u;
        if (gi < NG) g_count[gi] = 0;
    }
    const int rpb = (NN + 127) / 128;
    int r0 = b * rpb;
    int r1 = r0 + rpb; if (r1 > NN) r1 = NN;
    float s = 0.f, s2 = 0.f;
    for (int r = r0; r < r1; ++r) {
        float v = X[(size_t)r * F + t];
        s += v; s2 += v * v;
    }
    g_psums[b * F + t] = s;
    g_psumsq[b * F + t] = s2;
    __threadfence();
    __shared__ int lastFlag;
    if (t == 0) lastFlag = (atomicAdd(&g_bn_ctr[which], 1) == 127) ? 1 : 0;
    __syncthreads();
    if (lastFlag) {
        float ss = 0.f, ss2 = 0.f;
        for (int bb = 0; bb < 128; ++bb) {
            ss += g_psums[bb * F + t];
            ss2 += g_psumsq[bb * F + t];
        }
        float m = ss * (1.f / NN);
        float var = ss2 * (1.f / NN) - m * m;
        float sc = gam[t] * rsqrtf(var + BN_EPS);
        g_scale[t] = sc;
        g_shift[t] = bet[t] - m * sc;
        if (t == 0) g_bn_ctr[which] = 0;   // self-reset
    }
}
__global__ void k_bn_elu_split(const float4* __restrict__ X, __nv_bfloat162* __restrict__ hi,
                               __nv_bfloat162* __restrict__ lo, int total4, int fmask4) {
    int i = blockIdx.x * blockDim.x + threadIdx.x;
    if (i < total4) {
        int c4 = (i & fmask4) << 2;
        float4 v = X[i];
        float4 sc = *(const float4*)&g_scale[c4];
        float4 sh = *(const float4*)&g_shift[c4];
        float a = fmaf(v.x, sc.x, sh.x); a = a > 0.f ? a : expm1f(a);
        float b = fmaf(v.y, sc.y, sh.y); b = b > 0.f ? b : expm1f(b);
        float cc = fmaf(v.z, sc.z, sh.z); cc = cc > 0.f ? cc : expm1f(cc);
        float d = fmaf(v.w, sc.w, sh.w); d = d > 0.f ? d : expm1f(d);
        __nv_bfloat16 ha = __float2bfloat16(a), hb = __float2bfloat16(b);
        __nv_bfloat16 hc = __float2bfloat16(cc), hd = __float2bfloat16(d);
        hi[2 * i]     = __nv_bfloat162(ha, hb);
        hi[2 * i + 1] = __nv_bfloat162(hc, hd);
        lo[2 * i]     = __nv_bfloat162(__float2bfloat16(a - __bfloat162float(ha)),
                                       __float2bfloat16(b - __bfloat162float(hb)));
        lo[2 * i + 1] = __nv_bfloat162(__float2bfloat16(cc - __bfloat162float(hc)),
                                       __float2bfloat16(d - __bfloat162float(hd)));
    }
}

// ---------------- pooling (fused final BN+ELU + graph counts) ----------------
__global__ void __launch_bounds__(128)
k_pool_bn(const float* __restrict__ X, const int* __restrict__ batch) {
    int t = threadIdx.x;
    float sc = g_scale[t], sh = g_shift[t];
    int r0 = blockIdx.x * 256;
    int r1 = r0 + 256; if (r1 > NN) r1 = NN;
    if (r0 >= NN) return;
    int cur = batch[r0];
    float s = 0.f, m = -3.4e38f;
    int runlen = 0;
    for (int r = r0; r < r1; ++r) {
        int g = batch[r];
        if (g != cur) {
            atomicAdd(&g_psum[cur * 128 + t], s);
            atomicMax(&g_pmax[cur * 128 + t], enc_f(m));
            if (t == 0) atomicAdd(&g_count[cur], runlen);
            s = 0.f; m = -3.4e38f; cur = g; runlen = 0;
        }
        float v = X[(size_t)r * 128 + t] * sc + sh;
        v = v > 0.f ? v : expm1f(v);
        s += v; m = fmaxf(m, v);
        ++runlen;
    }
    atomicAdd(&g_psum[cur * 128 + t], s);
    atomicMax(&g_pmax[cur * 128 + t], enc_f(m));
    if (t == 0) atomicAdd(&g_count[cur], runlen);
}

// ---------------- classifier ----------------
__global__ void __launch_bounds__(256)
k_classifier(const float* __restrict__ cw1, const float* __restrict__ cb1,
             const float* __restrict__ cw2, const float* __restrict__ cb2,
             float* __restrict__ out) {
    __shared__ float s_emb[256];
    __shared__ float s_hid[256];
    int g = blockIdx.x, t = threadIdx.x;
    if (t < 128) {
        float c = (float)g_count[g];
        c = fmaxf(c, 1.f);
        s_emb[t] = g_psum[g * 128 + t] / c;
        s_emb[128 + t] = dec_f(g_pmax[g * 128 + t]);
    }
    __syncthreads();
    float a = cb1[t];
    const float* wr = cw1 + (size_t)t * 256;
    for (int j = 0; j < 256; j++) a += s_emb[j] * wr[j];
    s_hid[t] = fmaxf(a, 0.f);
    __syncthreads();
    if (t < 20) {
        float o = cb2[t];
        const float* w2 = cw2 + (size_t)t * 256;
        for (int j = 0; j < 256; j++) o += s_hid[j] * w2[j];
        out[g * 20 + t] = o;
    }
}

// ---------------- launch ----------------
extern "C" void kernel_launch(void* const* d_in, const int* in_sizes, int n_in,
                              void* d_out, int out_size) {
    const int*   x     = (const int*)d_in[0];
    const int*   ei    = (const int*)d_in[1];
    const float* depth = (const float*)d_in[2];
    const int*   batch = (const int*)d_in[3];
    const float* embt  = (const float*)d_in[4];
    const float* dw    = (const float*)d_in[5];
    const float* db    = (const float*)d_in[6];
    const float* W0  = (const float*)d_in[7];
    const float* as0 = (const float*)d_in[8];
    const float* ad0 = (const float*)d_in[9];
    const float* b0  = (const float*)d_in[10];
    const float* g0  = (const float*)d_in[11];
    const float* be0 = (const float*)d_in[12];
    const float* W1  = (const float*)d_in[13];
    const float* as1 = (const float*)d_in[14];
    const float* ad1 = (const float*)d_in[15];
    const float* b1  = (const float*)d_in[16];
    const float* g1  = (const float*)d_in[17];
    const float* be1 = (const float*)d_in[18];
    const float* W2  = (const float*)d_in[19];
    const float* as2 = (const float*)d_in[20];
    const float* ad2 = (const float*)d_in[21];
    const float* b2  = (const float*)d_in[22];
    const float* g2  = (const float*)d_in[23];
    const float* be2 = (const float*)d_in[24];
    const float* cw1 = (const float*)d_in[25];
    const float* cb1 = (const float*)d_in[26];
    const float* cw2 = (const float*)d_in[27];
    const float* cb2 = (const float*)d_in[28];
    float* out = (float*)d_out;

    float *pO = nullptr;
    __half *pX16 = nullptr;
    __nv_bfloat16 *pAh = nullptr, *pAl = nullptr, *pBh = nullptr, *pBl = nullptr;
    cudaGetSymbolAddress((void**)&pX16, g_X16);
    cudaGetSymbolAddress((void**)&pO, g_O);
    cudaGetSymbolAddress((void**)&pAh, g_Ah);
    cudaGetSymbolAddress((void**)&pAl, g_Al);
    cudaGetSymbolAddress((void**)&pBh, g_Bh);
    cudaGetSymbolAddress((void**)&pBl, g_Bl);

    cudaFuncSetAttribute(k_mma_gemm, cudaFuncAttributeMaxDynamicSharedMemorySize, GEMM_SMEM);

    const int MB = (NN + 127) / 128;

    // CSR build (5 kernels)
    k_init_deg<<<(NN + 255) / 256, 256>>>();
    k_count_deg<<<(NE + 255) / 256, 256>>>(ei);
    k_scan_blocks<<<(NN + 1023) / 1024, 1024>>>();
    k_add_off<<<(NN + 255) / 256, 256>>>();
    k_fill_col<<<(NEP + 255) / 256, 256>>>(ei);

    // ---- layer 0 (fully algebraic; X0 and its logits never materialized) ----
    k_w0_table<<<201, 512>>>(embt, W0, db, dw, as0, ad0);
    k_gather0<<<NN, 128>>>(x, depth, b0, pO);
    k_bn_stats_final<<<128, 512>>>(pO, 512, g0, be0, 0);
    k_bn_elu_split<<<(NN * 128 + 255) / 256, 256>>>((const float4*)pO,
        (__nv_bfloat162*)pAh, (__nv_bfloat162*)pAl, NN * 128, 127);

    // ---- layer 1: 512 -> 4x128 concat ----
    k_cvt_split4<<<(512 * 128 + 255) / 256, 256>>>((const float4*)W1, (__nv_bfloat162*)pBh, (__nv_bfloat162*)pBl, 512 * 128);
    k_mma_gemm<<<dim3(4, MB), 256, GEMM_SMEM>>>(pAh, pAl, pBh, pBl, pX16, NN, 512, 512, as1, ad1);
    k_gather4<<<NN, 128>>>(pX16, b1, pO);
    k_bn_stats_final<<<128, 512>>>(pO, 512, g1, be1, 1);
    k_bn_elu_split<<<(NN * 128 + 255) / 256, 256>>>((const float4*)pO,
        (__nv_bfloat162*)pAh, (__nv_bfloat162*)pAl, NN * 128, 127);

    // ---- layer 2: 512 -> 128, 1 head ----
    k_cvt_split4<<<(128 * 128 + 255) / 256, 256>>>((const float4*)W2, (__nv_bfloat162*)pBh, (__nv_bfloat162*)pBl, 128 * 128);
    k_mma_gemm<<<dim3(1, MB), 256, GEMM_SMEM>>>(pAh, pAl, pBh, pBl, pX16, NN, 128, 512, as2, ad2);
    k_gather1<<<(NN + 3) / 4, 128>>>(pX16, b2, pO);
    k_bn_stats_final<<<128, 128>>>(pO, 128, g2, be2, 2);   // also inits pooling arrays

    // ---- pooling (fused BN+ELU+counts) + classifier ----
    k_pool_bn<<<(NN + 255) / 256, 128>>>(pO, batch);
    k_classifier<<<NG, 256>>>(cw1, cb1, cw2, cb2, out);
}